// round 8
// baseline (speedup 1.0000x reference)
#include <cuda_runtime.h>
#include <cuda_fp16.h>
#include <cstdint>

#define CC   3
#define OO   8
#define HH   128
#define WW   128
#define HO   124
#define WO   124
#define P25  25

#define ROWSPAN 31
#define XT_W  36                  // 32 + 4 halo
#define XT_H  35                  // 31 + 4 halo

// One output row from a 6-slot ring (slot = xrow % 6). BASE = out row % 6.
// w[p] = (x, -x) half2; kp[p] = (-K_hit, +K_miss) half2.
// min over both halves of (w + kp) yields (hit, -miss).
template<int BASE>
__device__ __forceinline__ float row_compute6(const __half2* __restrict__ w,
                                              const __half2* __restrict__ kp)
{
    __half2 cu[5];
#pragma unroll
    for (int u = 0; u < 5; ++u) {
        const int s = ((BASE + u) % 6) * 5;
        __half2 acc = __hadd2(w[s], kp[u * 5]);
#pragma unroll
        for (int v = 1; v < 5; ++v)
            acc = __hmin2(acc, __hadd2(w[s + v], kp[u * 5 + v]));
        cu[u] = acc;
    }
    const __half2 r = __hmin2(__hmin2(__hmin2(cu[0], cu[1]),
                                      __hmin2(cu[2], cu[3])), cu[4]);
    return __low2float(r) + __high2float(r);   // hit - miss
}

// Double step: load x rows (rbase+J+4, rbase+J+5) into slots (J+4)%6,(J+5)%6;
// compute output rows rbase+J (BASE=J) and rbase+J+1 (BASE=J+1). J in {0,2,4}.
#define DSTEP(J)                                                                  \
    do {                                                                          \
        const __half2* nr0 = sxr + ((J) + 4) * XT_W;                              \
        const __half2* nr1 = nr0 + XT_W;                                          \
        _Pragma("unroll")                                                         \
        for (int v = 0; v < 5; ++v) {                                             \
            w[(((J) + 4) % 6) * 5 + v] = nr0[v];                                  \
            w[(((J) + 5) % 6) * 5 + v] = nr1[v];                                  \
        }                                                                         \
        const float r0 = row_compute6<(J)>(w, kp);                                \
        const float r1 = row_compute6<((J) + 1) % 6>(w, kp);                      \
        op[0]  = r0;                                                              \
        op[WO] = r1;                                                              \
        op += 2 * WO;                                                             \
    } while (0)

__global__ __launch_bounds__(256, 3)
void mnn_kernel(const float* __restrict__ x,
                const float* __restrict__ kh_g,
                const float* __restrict__ km_g,
                float* __restrict__ out)
{
    __shared__ __half2 sxh[XT_H * XT_W];   // (x, -x) tile: 35 x 36

    const int tx  = threadIdx.x;           // 0..31 column
    const int o   = threadIdx.y;           // 0..7  output channel
    const int tid = o * 32 + tx;

    // Overlapping x-tiles: wo0 in {0,30,61,92} -> all store lanes in-range
    // (overlap columns rewritten with identical values; deterministic).
    const int wo0 = (92 * blockIdx.x) / 3;
    const int ho0 = blockIdx.y * ROWSPAN;  // 124 = 4*31 exact
    const int bc  = blockIdx.z;            // b*CC + c
    const int b   = bc / CC;
    const int c   = bc % CC;

    // ---- weights first: 50 LDGs in flight while we stage the x tile ----
    const float* __restrict__ khp = kh_g + (size_t)(o * CC + c) * P25;
    const float* __restrict__ kmp = km_g + (size_t)(o * CC + c) * P25;
    float khr[P25], kmr[P25];
#pragma unroll
    for (int p = 0; p < P25; ++p) {
        khr[p] = __ldg(khp + p);
        kmr[p] = __ldg(kmp + p);
    }

    // ---- stage x tile as (x, -x) half2; all indices in-bounds ----
    const float* __restrict__ xb = x + (size_t)bc * HH * WW;
    for (int i = tid; i < XT_H * XT_W; i += 256) {
        const int rr  = i / XT_W;
        const int cc2 = i % XT_W;
        const float v = xb[(ho0 + rr) * WW + wo0 + cc2];
        const __half h = __float2half_rn(v);
        sxh[i] = __halves2half2(h, __hneg(h));
    }

    __half2 kp[P25];
#pragma unroll
    for (int p = 0; p < P25; ++p)
        kp[p] = __halves2half2(__float2half_rn(-khr[p]),
                               __float2half_rn( kmr[p]));
    __syncthreads();

    // ---- ring prologue: x rows 0..3 into slots 0..3 ----
    __half2 w[30];                          // 6-row ring, 5 taps per row
#pragma unroll
    for (int i = 0; i < 4; ++i)
#pragma unroll
        for (int v = 0; v < 5; ++v)
            w[i * 5 + v] = sxh[i * XT_W + tx + v];

    float* __restrict__ op =
        out + ((size_t)(b * OO * CC + o * CC + c) * HO + ho0) * WO + wo0 + tx;

    const __half2* sxr = sxh + tx;          // advances 6 rows per group

    // ---- 5 groups x (3 double-steps = 6 rows) = rows 0..29 ----
#pragma unroll 1
    for (int g = 0; g < 5; ++g) {
        DSTEP(0);
        DSTEP(2);
        DSTEP(4);
        sxr += 6 * XT_W;
    }

    // ---- tail: output row 30 (x rows 30..34; row 34 -> slot 4) ----
    {
        const __half2* nr = sxh + 34 * XT_W + tx;
#pragma unroll
        for (int v = 0; v < 5; ++v)
            w[4 * 5 + v] = nr[v];
        *op = row_compute6<0>(w, kp);
    }
}

extern "C" void kernel_launch(void* const* d_in, const int* in_sizes, int n_in,
                              void* d_out, int out_size)
{
    const float* x     = (const float*)d_in[0];
    const float* K_hit = (const float*)d_in[1];
    const float* K_mis = (const float*)d_in[2];
    float* out = (float*)d_out;

    dim3 grid(4, 4, OO * CC);     // 384 blocks, 3/SM cap -> single wave
    dim3 block(32, 8);
    mnn_kernel<<<grid, block>>>(x, K_hit, K_mis, out);
}

// round 9
// speedup vs baseline: 1.0276x; 1.0276x over previous
#include <cuda_runtime.h>
#include <cuda_fp16.h>
#include <cstdint>

#define CC   3
#define OO   8
#define HH   128
#define WW   128
#define HO   124
#define WO   124
#define P25  25

#define ROWSPAN 21                // 6 overlapping row-tiles: 0,21,42,63,84,103
#define XT_W  36                  // 32 + 4 halo
#define XT_H  25                  // 21 + 4 halo

// One output row from the 5-slot ring (slot = xrow % 5), phase J = row % 5.
// w[p] = (x, -x) half2; kp[p] = (-K_hit, +K_miss) half2.
// min over both halves of (w + kp) yields (hit, -miss).
template<int J>
__device__ __forceinline__ float row_compute(const __half2* __restrict__ w,
                                             const __half2* __restrict__ kp)
{
    __half2 cu[5];
#pragma unroll
    for (int u = 0; u < 5; ++u) {
        const int s = ((J + u) % 5) * 5;
        __half2 acc = __hadd2(w[s], kp[u * 5]);
#pragma unroll
        for (int v = 1; v < 5; ++v)
            acc = __hmin2(acc, __hadd2(w[s + v], kp[u * 5 + v]));
        cu[u] = acc;
    }
    const __half2 r = __hmin2(__hmin2(__hmin2(cu[0], cu[1]),
                                      __hmin2(cu[2], cu[3])), cu[4]);
    return __low2float(r) + __high2float(r);   // hit - miss
}

// Load x row (rbase+J+4) into ring slot (J+4)%5, compute output row rbase+J,
// store unconditionally (overlapping tiles keep every lane in-range).
#define ROW_STEP(J)                                                              \
    do {                                                                         \
        const __half2* nr = sxr + ((J) + 4) * XT_W;                              \
        _Pragma("unroll")                                                        \
        for (int v = 0; v < 5; ++v)                                              \
            w[(((J) + 4) % 5) * 5 + v] = nr[v];                                  \
        *op = row_compute<(J)>(w, kp);                                           \
        op += WO;                                                                \
    } while (0)

__global__ __launch_bounds__(256, 4)
void mnn_kernel(const float* __restrict__ x,
                const float* __restrict__ kh_g,
                const float* __restrict__ km_g,
                float* __restrict__ out)
{
    __shared__ __half2 sxh[XT_H * XT_W];   // (x, -x) tile: 25 x 36

    const int tx  = threadIdx.x;           // 0..31 column
    const int o   = threadIdx.y;           // 0..7  output channel
    const int tid = o * 32 + tx;

    // Overlapping tiles in both axes -> every store lane in-range; overlap
    // cells are rewritten with identical values (deterministic).
    const int wo0 = (92 * blockIdx.x) / 3;            // {0,30,61,92}
    const int ho0 = (blockIdx.y == 5) ? 103 : blockIdx.y * ROWSPAN;
    const int bc  = blockIdx.z;                        // b*CC + c
    const int b   = bc / CC;
    const int c   = bc % CC;

    // ---- weight LDGs first: latency overlaps the x-tile staging ----
    const float* __restrict__ khp = kh_g + (size_t)(o * CC + c) * P25;
    const float* __restrict__ kmp = km_g + (size_t)(o * CC + c) * P25;
    float khr[P25], kmr[P25];
#pragma unroll
    for (int p = 0; p < P25; ++p) {
        khr[p] = __ldg(khp + p);
        kmr[p] = __ldg(kmp + p);
    }

    // ---- stage x tile as (x, -x) half2; all indices in-bounds ----
    const float* __restrict__ xb = x + (size_t)bc * HH * WW;
    for (int i = tid; i < XT_H * XT_W; i += 256) {
        const int rr  = i / XT_W;
        const int cc2 = i % XT_W;
        const float v = xb[(ho0 + rr) * WW + wo0 + cc2];
        const __half h = __float2half_rn(v);
        sxh[i] = __halves2half2(h, __hneg(h));
    }

    __half2 kp[P25];
#pragma unroll
    for (int p = 0; p < P25; ++p)
        kp[p] = __halves2half2(__float2half_rn(-khr[p]),
                               __float2half_rn( kmr[p]));
    __syncthreads();

    // ---- ring prologue: x rows 0..3 into slots 0..3 ----
    __half2 w[P25];
#pragma unroll
    for (int i = 0; i < 4; ++i)
#pragma unroll
        for (int v = 0; v < 5; ++v)
            w[i * 5 + v] = sxh[i * XT_W + tx + v];

    float* __restrict__ op =
        out + ((size_t)(b * OO * CC + o * CC + c) * HO + ho0) * WO + wo0 + tx;

    const __half2* sxr = sxh + tx;          // advances 5 rows per chunk

    // ---- 4 chunks x 5 rows + 1 tail = 21 output rows ----
#pragma unroll 1
    for (int rc = 0; rc < 4; ++rc) {
        ROW_STEP(0);
        ROW_STEP(1);
        ROW_STEP(2);
        ROW_STEP(3);
        ROW_STEP(4);
        sxr += 5 * XT_W;
    }
    ROW_STEP(0);   // row 20
}

extern "C" void kernel_launch(void* const* d_in, const int* in_sizes, int n_in,
                              void* d_out, int out_size)
{
    const float* x     = (const float*)d_in[0];
    const float* K_hit = (const float*)d_in[1];
    const float* K_mis = (const float*)d_in[2];
    float* out = (float*)d_out;

    dim3 grid(4, 6, OO * CC);     // 576 blocks, cap 4/SM -> balanced single wave
    dim3 block(32, 8);
    mnn_kernel<<<grid, block>>>(x, K_hit, K_mis, out);
}